// round 2
// baseline (speedup 1.0000x reference)
#include <cuda_runtime.h>

typedef unsigned long long ULL;

// ---- problem constants ----
#define NPTS   25088          // 8*56*56
#define KCB    2048
#define CDIM   64
#define HW     3136           // 56*56
#define BSTRIDE 200704        // 64*3136 (feat batch stride)

// output offsets (floats) in d_out, tuple order: out_feat, assignment, distance, vq0_update
#define OUTF_OFF   0
#define ASSIGN_OFF 1605632
#define DIST_OFF   52985856
#define VQ_OFF     104366080

#define INVT 10.0f            // 1/temperature

__device__ float g_rowmin[NPTS];

#define FMA2(acc, a, b) asm("fma.rn.f32x2 %0, %1, %2, %0;" : "+l"(acc) : "l"(a), "l"(b))

// ---------------- K0: zero vq histogram ----------------
__global__ void k0_zero(float* __restrict__ out) {
    int i = blockIdx.x * blockDim.x + threadIdx.x;
    if (i < KCB) out[VQ_OFF + i] = 0.0f;
}

// ---------------- K1: distance GEMM + row min/argmin + vq ----------------
// grid 392 CTAs x 64 rows, 256 threads. k-tile = 256.
// smem layout (dynamic):
//   x2s  [64 j][64 row]  u64 {x,x}          32768 B
//   cpA  [64 j][32 col][4 floats]           32768 B   (pairs 0,1 of each 8-k group)
//   cpB  [64 j][32 col][4 floats]           32768 B   (pairs 2,3)
//   csq  [2048]                              8192 B
//   xsq  [64]                                 256 B
//   red  [64] u64                             512 B
#define K1_SMEM 107264

__global__ __launch_bounds__(256, 2) void k1_gemm(const float* __restrict__ feat,
                                                  const float* __restrict__ cbk,
                                                  float* __restrict__ out) {
    extern __shared__ char sm[];
    ULL*   x2s = (ULL*)sm;
    float* cpA = (float*)(sm + 32768);
    float* cpB = (float*)(sm + 65536);
    float* csq = (float*)(sm + 98304);
    float* xsq = (float*)(sm + 106496);
    ULL*   red = (ULL*)(sm + 106752);

    const int t  = threadIdx.x;
    const int pg = t & 31;      // k-group (8 codes)
    const int rg = t >> 5;      // row-group (8 rows) == warp id
    const int n0 = blockIdx.x * 64;
    const int b  = n0 / HW, hw0 = n0 % HW;
    const float* fb = feat + b * BSTRIDE + hw0;

    // load X -> x2s[j][row] = {x,x} packed
#pragma unroll
    for (int i = 0; i < 16; i++) {
        int idx = t + i * 256;
        int j = idx >> 6, row = idx & 63;
        float v = fb[j * HW + row];
        unsigned u = __float_as_uint(v);
        x2s[j * 64 + row] = ((ULL)u << 32) | (ULL)u;
    }
    if (t < 64) red[t] = ~0ULL;
    __syncthreads();

    // xsq per row
    if (t < 64) {
        float s = 0.f;
#pragma unroll 8
        for (int j = 0; j < 64; j++) {
            float v = __uint_as_float((unsigned)(x2s[j * 64 + t] & 0xffffffffULL));
            s = fmaf(v, v, s);
        }
        xsq[t] = s;
    }
    // csq for all 2048 codes (coalesced, warp-cooperative)
    {
        int w = t >> 5, lane = t & 31;
        for (int k2 = w; k2 < 1024; k2 += 8) {
            int k = k2 * 2 + (lane >> 4);
            float4 c4 = *(const float4*)(cbk + k * 64 + (lane & 15) * 4);
            float p = c4.x * c4.x + c4.y * c4.y + c4.z * c4.z + c4.w * c4.w;
#pragma unroll
            for (int o = 8; o >= 1; o >>= 1) p += __shfl_xor_sync(0xffffffffu, p, o);
            if ((lane & 15) == 0) csq[k] = p;
        }
    }

    ULL mp[8];
#pragma unroll
    for (int r = 0; r < 8; r++) mp[r] = ~0ULL;

    for (int kt = 0; kt < KCB; kt += 256) {
        __syncthreads();   // protect cpA/cpB reuse
        // load + transpose + pair-pack codebook tile (256 codes x 64)
#pragma unroll
        for (int i = 0; i < 16; i++) {
            int idx = t + i * 256;       // 4096 float4 chunks
            int kl = idx >> 4, jq = idx & 15;
            float4 v = *(const float4*)(cbk + (kt + kl) * 64 + jq * 4);
            int pr = kl >> 1, half = kl & 1, pgt = pr >> 2, pp = pr & 3;
            float* dst = (pp < 2) ? cpA : cpB;
            int ppo = (pp & 1) * 2 + half;
            const float* vv = (const float*)&v;
#pragma unroll
            for (int q = 0; q < 4; q++) {
                int j = jq * 4 + q;
                int col = pgt ^ ((j >> 2) & 31);   // xor swizzle
                dst[(j * 32 + col) * 4 + ppo] = vv[q];
            }
        }
        __syncthreads();

        ULL A[8][4];
#pragma unroll
        for (int r = 0; r < 8; r++)
#pragma unroll
            for (int p = 0; p < 4; p++) A[r][p] = 0ULL;

#pragma unroll 16
        for (int j = 0; j < 64; j++) {
            const ULL* xp = x2s + j * 64 + rg * 8;
            ulonglong2 x01 = ((const ulonglong2*)xp)[0];
            ulonglong2 x23 = ((const ulonglong2*)xp)[1];
            ulonglong2 x45 = ((const ulonglong2*)xp)[2];
            ulonglong2 x67 = ((const ulonglong2*)xp)[3];
            int g = j * 32 + (pg ^ ((j >> 2) & 31));
            ulonglong2 ca  = ((const ulonglong2*)cpA)[g];
            ulonglong2 cbv = ((const ulonglong2*)cpB)[g];
            FMA2(A[0][0], x01.x, ca.x); FMA2(A[0][1], x01.x, ca.y); FMA2(A[0][2], x01.x, cbv.x); FMA2(A[0][3], x01.x, cbv.y);
            FMA2(A[1][0], x01.y, ca.x); FMA2(A[1][1], x01.y, ca.y); FMA2(A[1][2], x01.y, cbv.x); FMA2(A[1][3], x01.y, cbv.y);
            FMA2(A[2][0], x23.x, ca.x); FMA2(A[2][1], x23.x, ca.y); FMA2(A[2][2], x23.x, cbv.x); FMA2(A[2][3], x23.x, cbv.y);
            FMA2(A[3][0], x23.y, ca.x); FMA2(A[3][1], x23.y, ca.y); FMA2(A[3][2], x23.y, cbv.x); FMA2(A[3][3], x23.y, cbv.y);
            FMA2(A[4][0], x45.x, ca.x); FMA2(A[4][1], x45.x, ca.y); FMA2(A[4][2], x45.x, cbv.x); FMA2(A[4][3], x45.x, cbv.y);
            FMA2(A[5][0], x45.y, ca.x); FMA2(A[5][1], x45.y, ca.y); FMA2(A[5][2], x45.y, cbv.x); FMA2(A[5][3], x45.y, cbv.y);
            FMA2(A[6][0], x67.x, ca.x); FMA2(A[6][1], x67.x, ca.y); FMA2(A[6][2], x67.x, cbv.x); FMA2(A[6][3], x67.x, cbv.y);
            FMA2(A[7][0], x67.y, ca.x); FMA2(A[7][1], x67.y, ca.y); FMA2(A[7][2], x67.y, cbv.x); FMA2(A[7][3], x67.y, cbv.y);
        }

        // epilogue: distance = xsq + csq - 2*dot ; write + min-track
        const int kbase = kt + pg * 8;
#pragma unroll
        for (int r = 0; r < 8; r++) {
            float xsv = xsq[rg * 8 + r];
            float d[8];
#pragma unroll
            for (int p = 0; p < 4; p++) {
                float lo = __uint_as_float((unsigned)(A[r][p] & 0xffffffffULL));
                float hi = __uint_as_float((unsigned)(A[r][p] >> 32));
                d[2 * p]     = fmaf(-2.f, lo, xsv + csq[kbase + 2 * p]);
                d[2 * p + 1] = fmaf(-2.f, hi, xsv + csq[kbase + 2 * p + 1]);
            }
            float* dp = out + DIST_OFF + (size_t)(n0 + rg * 8 + r) * KCB + kbase;
            *(float4*)dp       = make_float4(d[0], d[1], d[2], d[3]);
            *(float4*)(dp + 4) = make_float4(d[4], d[5], d[6], d[7]);
#pragma unroll
            for (int q = 0; q < 8; q++) {
                ULL pk = ((ULL)__float_as_uint(d[q]) << 32) | (ULL)(unsigned)(kbase + q);
                if (pk < mp[r]) mp[r] = pk;
            }
        }
    }

#pragma unroll
    for (int r = 0; r < 8; r++) atomicMin(&red[rg * 8 + r], mp[r]);
    __syncthreads();
    if (t < 64) {
        ULL pk = red[t];
        g_rowmin[n0 + t] = __uint_as_float((unsigned)(pk >> 32));
        atomicAdd(out + VQ_OFF + (unsigned)(pk & 0xffffffffULL), 1.0f);
    }
}

// ---------------- K2: softmax + transposed assignment + q_feat ----------------
// grid 1568 CTAs x 16 rows, 256 threads.
__global__ __launch_bounds__(256) void k2_softmax(const float* __restrict__ cbk,
                                                  float* __restrict__ out) {
    __shared__ float sT[128 * 17];
    __shared__ float zred[16 * 17];
    __shared__ float qacc[16 * 64];
    __shared__ float minv[16], zinv[16];

    const int t = threadIdx.x;
    const int row = t >> 4, sub = t & 15;
    const int n0 = blockIdx.x * 16;
    const int b = n0 / HW, hw0 = n0 % HW;
    const float* dist = out + DIST_OFF + (size_t)n0 * KCB;

    if (t < 16) minv[t] = g_rowmin[n0 + t];
#pragma unroll
    for (int i = 0; i < 4; i++) qacc[t + i * 256] = 0.f;
    __syncthreads();
    const float m = minv[row];

    // pass 1: Z
    float z = 0.f;
    for (int kt = 0; kt < KCB; kt += 128) {
        const float4* p4 = (const float4*)(dist + (size_t)row * KCB + kt + sub * 8);
        float4 a = p4[0], c = p4[1];
        float v[8] = {a.x, a.y, a.z, a.w, c.x, c.y, c.z, c.w};
#pragma unroll
        for (int q = 0; q < 8; q++) {
            float arg = (m - v[q]) * INVT;
            if (arg > -40.f) z += __expf(arg);
        }
    }
    zred[row * 17 + sub] = z;
    __syncthreads();
    if (t < 16) {
        float s = 0.f;
#pragma unroll
        for (int i = 0; i < 16; i++) s += zred[t * 17 + i];
        zinv[t] = 1.f / s;
    }
    __syncthreads();
    const float zi = zinv[row];

    // pass 2: probs -> assignment (transposed), sparse q_feat accumulation
    float* assign = out + ASSIGN_OFF + (size_t)b * KCB * HW + hw0;
    for (int kt = 0; kt < KCB; kt += 128) {
        const float4* p4 = (const float4*)(dist + (size_t)row * KCB + kt + sub * 8);
        float4 a = p4[0], c = p4[1];
        float v[8] = {a.x, a.y, a.z, a.w, c.x, c.y, c.z, c.w};
#pragma unroll
        for (int q = 0; q < 8; q++) {
            float arg = (m - v[q]) * INVT;
            float p = 0.f;
            if (arg > -40.f) p = __expf(arg) * zi;
            sT[(sub * 8 + q) * 17 + row] = p;
            if (p > 1e-10f) {
                const float* cr = cbk + (size_t)(kt + sub * 8 + q) * 64;
#pragma unroll 8
                for (int c2 = 0; c2 < 64; c2++) atomicAdd(&qacc[row * 64 + c2], p * cr[c2]);
            }
        }
        __syncthreads();
#pragma unroll
        for (int s = 0; s < 8; s++) {
            int kl = s * 16 + (t >> 4);
            int r2 = t & 15;
            assign[(size_t)(kt + kl) * HW + r2] = sT[kl * 17 + r2];
        }
        __syncthreads();
    }

    // out_feat = q_feat (gate = 0)
    float* of = out + OUTF_OFF + (size_t)b * BSTRIDE + hw0;
#pragma unroll
    for (int i = 0; i < 4; i++) {
        int idx = t + i * 256;
        int c2 = idx >> 4, r2 = idx & 15;
        of[c2 * HW + r2] = qacc[r2 * 64 + c2];
    }
}

extern "C" void kernel_launch(void* const* d_in, const int* in_sizes, int n_in,
                              void* d_out, int out_size) {
    const float* feat = (const float*)d_in[0];
    const float* cbk  = (const float*)d_in[1];
    float* out = (float*)d_out;

    cudaFuncSetAttribute(k1_gemm, cudaFuncAttributeMaxDynamicSharedMemorySize, K1_SMEM);

    k0_zero<<<8, 256>>>(out);
    k1_gemm<<<NPTS / 64, 256, K1_SMEM>>>(feat, cbk, out);
    k2_softmax<<<NPTS / 16, 256>>>(cbk, out);
}

// round 3
// speedup vs baseline: 1.5380x; 1.5380x over previous
#include <cuda_runtime.h>

typedef unsigned long long ULL;

// ---- problem constants ----
#define NPTS   25088          // 8*56*56
#define KCB    2048
#define CDIM   64
#define HW     3136           // 56*56
#define BSTRIDE 200704        // 64*3136

// output offsets (floats), tuple order: out_feat, assignment, distance, vq0_update
#define OUTF_OFF   0
#define ASSIGN_OFF 1605632
#define DIST_OFF   52985856
#define VQ_OFF     104366080

#define INVT 10.0f

__device__ float g_rowmin[NPTS];
__device__ float g_z[NPTS];
__device__ float g_csq[KCB];

#define FMA2(acc, a, b) asm("fma.rn.f32x2 %0, %1, %2, %0;" : "+l"(acc) : "l"(a), "l"(b))

// ---------------- K0: zero vq histogram + precompute codebook sq norms ----------------
__global__ void k0_prep(const float* __restrict__ cbk, float* __restrict__ out) {
    int k = blockIdx.x * blockDim.x + threadIdx.x;
    if (k < KCB) {
        out[VQ_OFF + k] = 0.0f;
        const float4* c4 = (const float4*)(cbk + k * 64);
        float s = 0.f;
#pragma unroll
        for (int i = 0; i < 16; i++) {
            float4 v = c4[i];
            s += v.x * v.x + v.y * v.y + v.z * v.z + v.w * v.w;
        }
        g_csq[k] = s;
    }
}

// ---------------- K1: distance GEMM + fused online softmax (m, Z, argmin) ----------------
// 392 CTAs x 64 rows, 256 threads, k-tile = 128.
// smem: x2s [64 j][64 row] u64 (32KB) | cp [64 j][32 col] ulonglong2 (32KB) | xsq[64]
#define K1_SMEM (32768 + 32768 + 256)

__global__ __launch_bounds__(256, 2) void k1_gemm(const float* __restrict__ feat,
                                                  const float* __restrict__ cbk,
                                                  float* __restrict__ out) {
    extern __shared__ char sm[];
    ULL*        x2s = (ULL*)sm;
    ulonglong2* cp  = (ulonglong2*)(sm + 32768);
    float*      xsq = (float*)(sm + 65536);

    const int t  = threadIdx.x;
    const int pg = t & 31;      // lane: 4 codes
    const int rg = t >> 5;      // warp: 8 rows
    const int n0 = blockIdx.x * 64;
    const int b  = n0 / HW, hw0 = n0 % HW;
    const float* fb = feat + b * BSTRIDE + hw0;

    // stage X: x2s[j][row] = {x,x}
#pragma unroll
    for (int i = 0; i < 16; i++) {
        int idx = t + i * 256;
        int j = idx >> 6, row = idx & 63;
        unsigned u = __float_as_uint(fb[j * HW + row]);
        x2s[j * 64 + row] = ((ULL)u << 32) | (ULL)u;
    }
    __syncthreads();
    if (t < 64) {
        float s = 0.f;
#pragma unroll 8
        for (int j = 0; j < 64; j++) {
            float v = __uint_as_float((unsigned)(x2s[j * 64 + t] & 0xffffffffULL));
            s = fmaf(v, v, s);
        }
        xsq[t] = s;
    }

    float mr[8], zr[8];
    int   ir[8];
#pragma unroll
    for (int r = 0; r < 8; r++) { mr[r] = __int_as_float(0x7f800000); zr[r] = 0.f; ir[r] = 0; }

    for (int kt = 0; kt < KCB; kt += 128) {
        __syncthreads();
        // stage codebook tile 128 codes x 64 ch, pair-packed + xor swizzle
#pragma unroll
        for (int i = 0; i < 8; i++) {
            int idx = t + i * 256;
            int kl = idx >> 4, jq = idx & 15;
            float4 v = *(const float4*)(cbk + (size_t)(kt + kl) * 64 + jq * 4);
            const float* vv = (const float*)&v;
            int part = kl & 3, grp = kl >> 2;
#pragma unroll
            for (int q = 0; q < 4; q++) {
                int j = jq * 4 + q;
                int col = grp ^ (j & 31);
                ((float*)cp)[(j * 32 + col) * 4 + part] = vv[q];
            }
        }
        __syncthreads();

        ULL A[8][2];
#pragma unroll
        for (int r = 0; r < 8; r++) { A[r][0] = 0ULL; A[r][1] = 0ULL; }

#pragma unroll 16
        for (int j = 0; j < 64; j++) {
            const ULL* xp = x2s + j * 64 + rg * 8;
            ulonglong2 x01 = ((const ulonglong2*)xp)[0];
            ulonglong2 x23 = ((const ulonglong2*)xp)[1];
            ulonglong2 x45 = ((const ulonglong2*)xp)[2];
            ulonglong2 x67 = ((const ulonglong2*)xp)[3];
            ulonglong2 cv = cp[j * 32 + (pg ^ (j & 31))];
            FMA2(A[0][0], x01.x, cv.x); FMA2(A[0][1], x01.x, cv.y);
            FMA2(A[1][0], x01.y, cv.x); FMA2(A[1][1], x01.y, cv.y);
            FMA2(A[2][0], x23.x, cv.x); FMA2(A[2][1], x23.x, cv.y);
            FMA2(A[3][0], x23.y, cv.x); FMA2(A[3][1], x23.y, cv.y);
            FMA2(A[4][0], x45.x, cv.x); FMA2(A[4][1], x45.x, cv.y);
            FMA2(A[5][0], x45.y, cv.x); FMA2(A[5][1], x45.y, cv.y);
            FMA2(A[6][0], x67.x, cv.x); FMA2(A[6][1], x67.x, cv.y);
            FMA2(A[7][0], x67.y, cv.x); FMA2(A[7][1], x67.y, cv.y);
        }

        // epilogue: distance + online (m, z, argmin)
        const int kbase = kt + pg * 4;
        float4 cs = *(const float4*)(g_csq + kbase);
#pragma unroll
        for (int r = 0; r < 8; r++) {
            float xs = xsq[rg * 8 + r];
            float d0 = fmaf(-2.f, __uint_as_float((unsigned)(A[r][0] & 0xffffffffULL)), xs + cs.x);
            float d1 = fmaf(-2.f, __uint_as_float((unsigned)(A[r][0] >> 32)),           xs + cs.y);
            float d2 = fmaf(-2.f, __uint_as_float((unsigned)(A[r][1] & 0xffffffffULL)), xs + cs.z);
            float d3 = fmaf(-2.f, __uint_as_float((unsigned)(A[r][1] >> 32)),           xs + cs.w);
            *(float4*)(out + DIST_OFF + (size_t)(n0 + rg * 8 + r) * KCB + kbase) =
                make_float4(d0, d1, d2, d3);
            float dv[4] = {d0, d1, d2, d3};
#pragma unroll
            for (int q = 0; q < 4; q++) {
                float d = dv[q];
                bool lt = d < mr[r];
                float e = __expf((fminf(d, mr[r]) - fmaxf(d, mr[r])) * INVT);
                zr[r] = lt ? fmaf(zr[r], e, 1.0f) : (zr[r] + e);
                ir[r] = lt ? (kbase + q) : ir[r];
                mr[r] = fminf(mr[r], d);
            }
        }
    }

    // warp-level merge of per-lane (m, z, idx) for the 8 rows this warp owns
#pragma unroll
    for (int r = 0; r < 8; r++) {
        float m = mr[r], z = zr[r];
        int idx = ir[r];
#pragma unroll
        for (int o = 16; o >= 1; o >>= 1) {
            float m2 = __shfl_xor_sync(0xffffffffu, m, o);
            float z2 = __shfl_xor_sync(0xffffffffu, z, o);
            int   i2 = __shfl_xor_sync(0xffffffffu, idx, o);
            float mn = fminf(m, m2);
            z = z * __expf((mn - m) * INVT) + z2 * __expf((mn - m2) * INVT);
            idx = (m2 < m) ? i2 : idx;
            m = mn;
        }
        if ((t & 31) == 0) {
            int row = n0 + rg * 8 + r;
            g_rowmin[row] = m;
            g_z[row] = z;
            atomicAdd(out + VQ_OFF + idx, 1.0f);
        }
    }
}

// ---------------- K2: single pass: probs -> assignment (transposed) + q_feat ----------------
// 1568 CTAs x 16 rows, 256 threads.
__global__ __launch_bounds__(256) void k2_softmax(const float* __restrict__ cbk,
                                                  float* __restrict__ out) {
    __shared__ float sT[128 * 17];
    __shared__ float qacc[16 * 65];
    __shared__ float listP[16 * 64];
    __shared__ int   listK[16 * 64];
    __shared__ int   cnt[16];
    __shared__ float minv[16], zinv[16];

    const int t = threadIdx.x;
    const int row = t >> 4, sub = t & 15;
    const int n0 = blockIdx.x * 16;
    const int b = n0 / HW, hw0 = n0 % HW;
    const float* dist = out + DIST_OFF + (size_t)n0 * KCB;

    if (t < 16) {
        minv[t] = g_rowmin[n0 + t];
        zinv[t] = __frcp_rn(g_z[n0 + t]);
        cnt[t] = 0;
    }
#pragma unroll
    for (int i = 0; i < 5; i++) {
        int idx = t + i * 256;
        if (idx < 16 * 65) qacc[idx] = 0.f;
    }
    __syncthreads();
    const float m = minv[row];
    const float zi = zinv[row];

    float* assign = out + ASSIGN_OFF + (size_t)b * KCB * HW + hw0;
    for (int kt = 0; kt < KCB; kt += 128) {
        const float4* p4 = (const float4*)(dist + (size_t)row * KCB + kt + sub * 8);
        float4 a = p4[0], c = p4[1];
        float v[8] = {a.x, a.y, a.z, a.w, c.x, c.y, c.z, c.w};
#pragma unroll
        for (int q = 0; q < 8; q++) {
            float p = __expf((m - v[q]) * INVT) * zi;
            sT[(sub * 8 + q) * 17 + row] = p;
            if (p > 1e-10f) {
                int pos = atomicAdd(&cnt[row], 1);
                if (pos < 64) {
                    listK[row * 64 + pos] = kt + sub * 8 + q;
                    listP[row * 64 + pos] = p;
                } else {  // overflow fallback (rare)
                    const float* cr = cbk + (size_t)(kt + sub * 8 + q) * 64;
#pragma unroll 8
                    for (int c2 = 0; c2 < 64; c2++)
                        atomicAdd(&qacc[row * 65 + c2], p * cr[c2]);
                }
            }
        }
        __syncthreads();
#pragma unroll
        for (int s = 0; s < 8; s++) {
            int kl = s * 16 + (t >> 4);
            int r2 = t & 15;
            assign[(size_t)(kt + kl) * HW + r2] = sT[kl * 17 + r2];
        }
        __syncthreads();
    }

    // q_feat: warp w accumulates rows 2w, 2w+1 from its list
    const int wid = t >> 5, lane = t & 31;
#pragma unroll
    for (int rr0 = 0; rr0 < 2; rr0++) {
        int rr = wid * 2 + rr0;
        int n = min(cnt[rr], 64);
        float a0 = 0.f, a1 = 0.f;
        for (int e = 0; e < n; e++) {
            int k = listK[rr * 64 + e];
            float p = listP[rr * 64 + e];
            a0 = fmaf(p, cbk[(size_t)k * 64 + lane], a0);
            a1 = fmaf(p, cbk[(size_t)k * 64 + 32 + lane], a1);
        }
        qacc[rr * 65 + lane] += a0;
        qacc[rr * 65 + 32 + lane] += a1;
    }
    __syncthreads();

    // out_feat = q_feat (gate = 0)
    float* of = out + OUTF_OFF + (size_t)b * BSTRIDE + hw0;
#pragma unroll
    for (int i = 0; i < 4; i++) {
        int idx = t + i * 256;
        int c2 = idx >> 4, r2 = idx & 15;
        of[c2 * HW + r2] = qacc[r2 * 65 + c2];
    }
}

extern "C" void kernel_launch(void* const* d_in, const int* in_sizes, int n_in,
                              void* d_out, int out_size) {
    const float* feat = (const float*)d_in[0];
    const float* cbk  = (const float*)d_in[1];
    float* out = (float*)d_out;

    cudaFuncSetAttribute(k1_gemm, cudaFuncAttributeMaxDynamicSharedMemorySize, K1_SMEM);

    k0_prep<<<8, 256>>>(cbk, out);
    k1_gemm<<<NPTS / 64, 256, K1_SMEM>>>(feat, cbk, out);
    k2_softmax<<<NPTS / 16, 256>>>(cbk, out);
}

// round 4
// speedup vs baseline: 1.5864x; 1.0315x over previous
#include <cuda_runtime.h>

typedef unsigned long long ULL;

// ---- problem constants ----
#define NPTS   25088          // 8*56*56
#define KCB    2048
#define CDIM   64
#define HW     3136           // 56*56
#define BSTRIDE 200704        // 64*3136

// output offsets (floats), tuple order: out_feat, assignment, distance, vq0_update
#define OUTF_OFF   0
#define ASSIGN_OFF 1605632
#define DIST_OFF   52985856
#define VQ_OFF     104366080

#define INVT 10.0f

__device__ float g_rowmin[NPTS];
__device__ float g_z[NPTS];
__device__ float g_csq[KCB];
__device__ float g_cbT[CDIM * KCB];   // transposed codebook [ch][code]

#define FMA2(acc, a, b) asm("fma.rn.f32x2 %0, %1, %2, %0;" : "+l"(acc) : "l"(a), "l"(b))

// ---------------- K0: transpose codebook + csq + zero vq ----------------
// 64 CTAs x 32 codes, 256 threads.
__global__ void k0_prep(const float* __restrict__ cbk, float* __restrict__ out) {
    __shared__ float s[32 * 65];
    const int t = threadIdx.x;
    const int k0 = blockIdx.x * 32;
#pragma unroll
    for (int i = 0; i < 8; i++) {
        int idx = t + i * 256;
        int kk = idx >> 6, c = idx & 63;
        s[kk * 65 + c] = cbk[(size_t)(k0 + kk) * 64 + c];
    }
    __syncthreads();
#pragma unroll
    for (int i = 0; i < 8; i++) {
        int idx = t + i * 256;
        int c = idx >> 5, kk = idx & 31;
        g_cbT[(size_t)c * KCB + k0 + kk] = s[kk * 65 + c];
    }
    if (t < 32) {
        float sum = 0.f;
#pragma unroll 16
        for (int c = 0; c < 64; c++) {
            float v = s[t * 65 + c];
            sum = fmaf(v, v, sum);
        }
        g_csq[k0 + t] = sum;
        out[VQ_OFF + k0 + t] = 0.0f;
    }
}

// ---------------- K1: distance GEMM + fused online softmax stats ----------------
// 392 CTAs x 64 rows, 256 threads, k-tile = 256 (8x8 per-thread tile).
// smem: x2s [64 j][64 row] u64 (32KB) | cp [64 j][256 code] float swizzled (64KB) | xsq[64]
#define K1_SMEM (32768 + 65536 + 256)

__global__ __launch_bounds__(256, 2) void k1_gemm(const float* __restrict__ feat,
                                                  float* __restrict__ out) {
    extern __shared__ char sm[];
    ULL*   x2s = (ULL*)sm;
    float* cp  = (float*)(sm + 32768);
    float* xsq = (float*)(sm + 98304);

    const int t    = threadIdx.x;
    const int lane = t & 31;     // lane: 8 codes
    const int rg   = t >> 5;     // warp: 8 rows
    const int n0   = blockIdx.x * 64;
    const int b    = n0 / HW, hw0 = n0 % HW;
    const float* fb = feat + (size_t)b * BSTRIDE + hw0;

    // stage X: x2s[j][row] = {x,x}
#pragma unroll
    for (int i = 0; i < 16; i++) {
        int idx = t + i * 256;
        int j = idx >> 6, row = idx & 63;
        unsigned u = __float_as_uint(fb[(size_t)j * HW + row]);
        x2s[j * 64 + row] = ((ULL)u << 32) | (ULL)u;
    }
    __syncthreads();
    if (t < 64) {
        float s = 0.f;
#pragma unroll 8
        for (int j = 0; j < 64; j++) {
            float v = __uint_as_float((unsigned)(x2s[j * 64 + t] & 0xffffffffULL));
            s = fmaf(v, v, s);
        }
        xsq[t] = s;
    }

    float mr[8], zr[8];
    int   ir[8];
#pragma unroll
    for (int r = 0; r < 8; r++) { mr[r] = __int_as_float(0x7f800000); zr[r] = 0.f; ir[r] = 0; }

    for (int kt = 0; kt < KCB; kt += 256) {
        __syncthreads();
        // stage codebook tile from transposed copy: cp[j][g^sw][4] (vec4 swizzle)
#pragma unroll
        for (int i = 0; i < 16; i++) {
            int idx = t + i * 256;
            int j = idx >> 6, g = idx & 63;
            float4 v = *(const float4*)(g_cbT + (size_t)j * KCB + kt + g * 4);
            int sw = (j >> 2) & 7;
            *(float4*)(cp + j * 256 + ((g ^ sw) << 2)) = v;
        }
        __syncthreads();

        ULL A[8][4];
#pragma unroll
        for (int r = 0; r < 8; r++)
#pragma unroll
            for (int p = 0; p < 4; p++) A[r][p] = 0ULL;

#pragma unroll 8
        for (int j = 0; j < 64; j++) {
            const ULL* xp = x2s + j * 64 + rg * 8;
            ulonglong2 x01 = ((const ulonglong2*)xp)[0];
            ulonglong2 x23 = ((const ulonglong2*)xp)[1];
            ulonglong2 x45 = ((const ulonglong2*)xp)[2];
            ulonglong2 x67 = ((const ulonglong2*)xp)[3];
            const float* bj = cp + j * 256;
            int sw = (j >> 2) & 7;
            ulonglong2 ca = *(const ulonglong2*)(bj + (((2 * lane) ^ sw) << 2));
            ulonglong2 cb = *(const ulonglong2*)(bj + (((2 * lane + 1) ^ sw) << 2));
            FMA2(A[0][0], x01.x, ca.x); FMA2(A[0][1], x01.x, ca.y); FMA2(A[0][2], x01.x, cb.x); FMA2(A[0][3], x01.x, cb.y);
            FMA2(A[1][0], x01.y, ca.x); FMA2(A[1][1], x01.y, ca.y); FMA2(A[1][2], x01.y, cb.x); FMA2(A[1][3], x01.y, cb.y);
            FMA2(A[2][0], x23.x, ca.x); FMA2(A[2][1], x23.x, ca.y); FMA2(A[2][2], x23.x, cb.x); FMA2(A[2][3], x23.x, cb.y);
            FMA2(A[3][0], x23.y, ca.x); FMA2(A[3][1], x23.y, ca.y); FMA2(A[3][2], x23.y, cb.x); FMA2(A[3][3], x23.y, cb.y);
            FMA2(A[4][0], x45.x, ca.x); FMA2(A[4][1], x45.x, ca.y); FMA2(A[4][2], x45.x, cb.x); FMA2(A[4][3], x45.x, cb.y);
            FMA2(A[5][0], x45.y, ca.x); FMA2(A[5][1], x45.y, ca.y); FMA2(A[5][2], x45.y, cb.x); FMA2(A[5][3], x45.y, cb.y);
            FMA2(A[6][0], x67.x, ca.x); FMA2(A[6][1], x67.x, ca.y); FMA2(A[6][2], x67.x, cb.x); FMA2(A[6][3], x67.x, cb.y);
            FMA2(A[7][0], x67.y, ca.x); FMA2(A[7][1], x67.y, ca.y); FMA2(A[7][2], x67.y, cb.x); FMA2(A[7][3], x67.y, cb.y);
        }

        // epilogue: distance + branchy online (m, z, argmin)
        const int kbase = kt + lane * 8;
        float4 cs0 = *(const float4*)(g_csq + kbase);
        float4 cs1 = *(const float4*)(g_csq + kbase + 4);
#pragma unroll
        for (int r = 0; r < 8; r++) {
            float xs = xsq[rg * 8 + r];
            float d[8];
            d[0] = fmaf(-2.f, __uint_as_float((unsigned)(A[r][0] & 0xffffffffULL)), xs + cs0.x);
            d[1] = fmaf(-2.f, __uint_as_float((unsigned)(A[r][0] >> 32)),           xs + cs0.y);
            d[2] = fmaf(-2.f, __uint_as_float((unsigned)(A[r][1] & 0xffffffffULL)), xs + cs0.z);
            d[3] = fmaf(-2.f, __uint_as_float((unsigned)(A[r][1] >> 32)),           xs + cs0.w);
            d[4] = fmaf(-2.f, __uint_as_float((unsigned)(A[r][2] & 0xffffffffULL)), xs + cs1.x);
            d[5] = fmaf(-2.f, __uint_as_float((unsigned)(A[r][2] >> 32)),           xs + cs1.y);
            d[6] = fmaf(-2.f, __uint_as_float((unsigned)(A[r][3] & 0xffffffffULL)), xs + cs1.z);
            d[7] = fmaf(-2.f, __uint_as_float((unsigned)(A[r][3] >> 32)),           xs + cs1.w);
            float* dp = out + DIST_OFF + (size_t)(n0 + rg * 8 + r) * KCB + kbase;
            *(float4*)dp       = make_float4(d[0], d[1], d[2], d[3]);
            *(float4*)(dp + 4) = make_float4(d[4], d[5], d[6], d[7]);
            float dmin = fminf(fminf(fminf(d[0], d[1]), fminf(d[2], d[3])),
                               fminf(fminf(d[4], d[5]), fminf(d[6], d[7])));
            if (dmin < mr[r] + 4.0f) {   // contributions beyond e^-40 ignored
#pragma unroll
                for (int q = 0; q < 8; q++) {
                    float dd = d[q];
                    bool lt = dd < mr[r];
                    float e = __expf((fminf(dd, mr[r]) - fmaxf(dd, mr[r])) * INVT);
                    zr[r] = lt ? fmaf(zr[r], e, 1.0f) : (zr[r] + e);
                    ir[r] = lt ? (kbase + q) : ir[r];
                    mr[r] = fminf(mr[r], dd);
                }
            }
        }
    }

    // merge (m, z, argmin) across the 32 lanes for each of this warp's 8 rows
#pragma unroll
    for (int r = 0; r < 8; r++) {
        float m = mr[r], z = zr[r];
        int idx = ir[r];
#pragma unroll
        for (int o = 16; o >= 1; o >>= 1) {
            float m2 = __shfl_xor_sync(0xffffffffu, m, o);
            float z2 = __shfl_xor_sync(0xffffffffu, z, o);
            int   i2 = __shfl_xor_sync(0xffffffffu, idx, o);
            float mn = fminf(m, m2);
            z = z * __expf((mn - m) * INVT) + z2 * __expf((mn - m2) * INVT);
            idx = (m2 < m) ? i2 : idx;
            m = mn;
        }
        if (lane == 0) {
            int row = n0 + rg * 8 + r;
            g_rowmin[row] = m;
            g_z[row] = z;
            atomicAdd(out + VQ_OFF + idx, 1.0f);
        }
    }
}

// ---------------- K2: probs -> transposed assignment + q_feat (single pass) ----------------
// 784 CTAs x 32 rows, 256 threads, k-tile 128.
__global__ __launch_bounds__(256) void k2_softmax(const float* __restrict__ cbk,
                                                  float* __restrict__ out) {
    __shared__ float sT[128 * 32];      // phys col = ((k>>4)*4 + row) & 31
    __shared__ float qacc[32 * 65];
    __shared__ float listP[32 * 64];
    __shared__ int   listK[32 * 64];
    __shared__ int   cnt[32];
    __shared__ float minv[32], zinv[32];

    const int t = threadIdx.x;
    const int row = t >> 3, sub = t & 7;
    const int n0 = blockIdx.x * 32;
    const int b = n0 / HW, hw0 = n0 % HW;
    const float* dist = out + DIST_OFF + (size_t)n0 * KCB;

    if (t < 32) {
        minv[t] = g_rowmin[n0 + t];
        zinv[t] = __frcp_rn(g_z[n0 + t]);
        cnt[t] = 0;
    }
#pragma unroll
    for (int i = 0; i < 9; i++) {
        int idx = t + i * 256;
        if (idx < 32 * 65) qacc[idx] = 0.f;
    }
    __syncthreads();
    const float m = minv[row];
    const float zi = zinv[row];

    float* assign = out + ASSIGN_OFF + (size_t)b * KCB * HW + hw0;
    for (int kt = 0; kt < KCB; kt += 128) {
        const float4* p4 = (const float4*)(dist + (size_t)row * KCB + kt + sub * 16);
        float4 v4[4];
#pragma unroll
        for (int i = 0; i < 4; i++) v4[i] = p4[i];
        const float* v = (const float*)v4;
#pragma unroll
        for (int q = 0; q < 16; q++) {
            float p = __expf((m - v[q]) * INVT) * zi;
            int kl = sub * 16 + q;
            sT[kl * 32 + ((sub * 4 + row) & 31)] = p;
            if (p > 1e-10f) {
                int pos = atomicAdd(&cnt[row], 1);
                if (pos < 64) {
                    listK[row * 64 + pos] = kt + kl;
                    listP[row * 64 + pos] = p;
                } else {  // overflow fallback (rare)
                    const float* cr = cbk + (size_t)(kt + kl) * 64;
#pragma unroll 8
                    for (int c2 = 0; c2 < 64; c2++)
                        atomicAdd(&qacc[row * 65 + c2], p * cr[c2]);
                }
            }
        }
        __syncthreads();
#pragma unroll
        for (int s = 0; s < 16; s++) {
            int kl = s * 8 + (t >> 5);
            int r2 = t & 31;
            assign[(size_t)(kt + kl) * HW + r2] = sT[kl * 32 + (((kl >> 4) * 4 + r2) & 31)];
        }
        __syncthreads();
    }

    // q_feat: warp w handles rows w, w+8, w+16, w+24
    const int wid = t >> 5, lane2 = t & 31;
#pragma unroll
    for (int rr = wid; rr < 32; rr += 8) {
        int n = min(cnt[rr], 64);
        float a0 = 0.f, a1 = 0.f;
        for (int e = 0; e < n; e++) {
            int k = listK[rr * 64 + e];
            float p = listP[rr * 64 + e];
            a0 = fmaf(p, cbk[(size_t)k * 64 + lane2], a0);
            a1 = fmaf(p, cbk[(size_t)k * 64 + 32 + lane2], a1);
        }
        qacc[rr * 65 + lane2] += a0;
        qacc[rr * 65 + 32 + lane2] += a1;
    }
    __syncthreads();

    // out_feat = q_feat (gate = 0)
    float* of = out + OUTF_OFF + (size_t)b * BSTRIDE + hw0;
#pragma unroll
    for (int i = 0; i < 8; i++) {
        int idx = t + i * 256;
        int c2 = idx >> 5, r2 = idx & 31;
        of[(size_t)c2 * HW + r2] = qacc[r2 * 65 + c2];
    }
}

extern "C" void kernel_launch(void* const* d_in, const int* in_sizes, int n_in,
                              void* d_out, int out_size) {
    const float* feat = (const float*)d_in[0];
    const float* cbk  = (const float*)d_in[1];
    float* out = (float*)d_out;

    cudaFuncSetAttribute(k1_gemm, cudaFuncAttributeMaxDynamicSharedMemorySize, K1_SMEM);

    k0_prep<<<64, 256>>>(cbk, out);
    k1_gemm<<<NPTS / 64, 256, K1_SMEM>>>(feat, out);
    k2_softmax<<<NPTS / 32, 256>>>(cbk, out);
}

// round 6
// speedup vs baseline: 2.1935x; 1.3827x over previous
#include <cuda_runtime.h>
#include <cuda_fp16.h>
#include <cstdint>

// ---- problem constants ----
#define NPTS   25088          // 8*56*56
#define KCB    2048
#define CDIM   64
#define HW     3136           // 56*56
#define BSTRIDE 200704        // 64*3136

// output offsets (floats), tuple order: out_feat, assignment, distance, vq0_update
#define OUTF_OFF   0
#define ASSIGN_OFF 1605632
#define DIST_OFF   52985856
#define VQ_OFF     104366080

#define INVT 10.0f

__device__ float  g_rowmin[NPTS];
__device__ float  g_z[NPTS];
__device__ float  g_csq[KCB];
__device__ __half g_cbH16[KCB * CDIM];   // fp16 hi part of codebook
__device__ __half g_cbL16[KCB * CDIM];   // fp16 residual lo part

// ---------------- K0: fp16 hi/lo codebook split + csq + zero vq ----------------
// 128 CTAs x 256 threads; thread = (code, float4-chunk)
__global__ void k0_prep(const float* __restrict__ cbk, float* __restrict__ out) {
    int gid = blockIdx.x * 256 + threadIdx.x;    // 0..32767
    int code = gid >> 4, f4 = gid & 15;
    float4 v = ((const float4*)cbk)[code * 16 + f4];
    __half hx = __float2half_rn(v.x), hy = __float2half_rn(v.y);
    __half hz = __float2half_rn(v.z), hw = __float2half_rn(v.w);
    __half lx = __float2half_rn(v.x - __half2float(hx));
    __half ly = __float2half_rn(v.y - __half2float(hy));
    __half lz = __float2half_rn(v.z - __half2float(hz));
    __half lw = __float2half_rn(v.w - __half2float(hw));
    ((__half2*)g_cbH16)[code * 32 + f4 * 2]     = __halves2half2(hx, hy);
    ((__half2*)g_cbH16)[code * 32 + f4 * 2 + 1] = __halves2half2(hz, hw);
    ((__half2*)g_cbL16)[code * 32 + f4 * 2]     = __halves2half2(lx, ly);
    ((__half2*)g_cbL16)[code * 32 + f4 * 2 + 1] = __halves2half2(lz, lw);
    float p = v.x * v.x + v.y * v.y + v.z * v.z + v.w * v.w;
#pragma unroll
    for (int o = 8; o >= 1; o >>= 1) p += __shfl_xor_sync(0xffffffffu, p, o);
    if (f4 == 0) {
        g_csq[code] = p;
        out[VQ_OFF + code] = 0.0f;
    }
}

// ---------------- K1: mma.sync fp16 3-term distance GEMM + fused stats ----------------
// 196 CTAs x 128 rows, 256 threads (8 warps x 16 rows), 16 col-tiles of 128 codes.
__device__ __forceinline__ void mma16816(float* c, uint32_t a0, uint32_t a1, uint32_t a2,
                                         uint32_t a3, uint32_t b0, uint32_t b1) {
    asm volatile(
        "mma.sync.aligned.m16n8k16.row.col.f32.f16.f16.f32 "
        "{%0,%1,%2,%3}, {%4,%5,%6,%7}, {%8,%9}, {%0,%1,%2,%3};"
        : "+f"(c[0]), "+f"(c[1]), "+f"(c[2]), "+f"(c[3])
        : "r"(a0), "r"(a1), "r"(a2), "r"(a3), "r"(b0), "r"(b1));
}

// smem layout (bytes)
#define PADA 68                          // floats per A row
#define SM_A    0                        // 128*68*4   = 34816
#define SM_CSQ  34816                    // 8192
#define SM_BH   43008                    // 128*36*4   = 18432
#define SM_BL   61440                    // 18432
#define K1_SMEM 79872

__global__ __launch_bounds__(256) void k1_mma(const float* __restrict__ feat,
                                              float* __restrict__ out) {
    extern __shared__ char sm[];
    float*    As   = (float*)(sm + SM_A);
    float*    csqs = (float*)(sm + SM_CSQ);
    uint32_t* Bh   = (uint32_t*)(sm + SM_BH);
    uint32_t* Bl   = (uint32_t*)(sm + SM_BL);

    const int t = threadIdx.x;
    const int wid = t >> 5, lane = t & 31;
    const int g = lane >> 2, t4 = lane & 3;
    const int n0 = blockIdx.x * 128;

    // stage A fp32 [row][ch] padded
#pragma unroll
    for (int i = 0; i < 32; i++) {
        int idx = t + i * 256;
        int ch = idx >> 7, row = idx & 127;
        int n = n0 + row, b = n / HW, hw = n - b * HW;
        As[row * PADA + ch] = feat[(size_t)b * BSTRIDE + (size_t)ch * HW + hw];
    }
#pragma unroll
    for (int i = 0; i < 2; i++) {
        int idx = t + i * 256;
        ((float4*)csqs)[idx] = ((const float4*)g_csq)[idx];
    }
    __syncthreads();

    // per-thread rows
    const int r0 = wid * 16 + g;      // and r0+8
    // xs for the two rows
    float xs0 = 0.f, xs1 = 0.f;
#pragma unroll 16
    for (int c = 0; c < 64; c++) {
        float v0 = As[r0 * PADA + c], v1 = As[(r0 + 8) * PADA + c];
        xs0 = fmaf(v0, v0, xs0);
        xs1 = fmaf(v1, v1, xs1);
    }

    // build resident A fragments (hi/lo), 4 k-steps
    uint32_t ah[4][4], al[4][4];
#pragma unroll
    for (int ks = 0; ks < 4; ks++) {
        int c0 = ks * 16 + 2 * t4;
#pragma unroll
        for (int p = 0; p < 4; p++) {
            int row = (p & 1) ? (r0 + 8) : r0;
            int cc = c0 + ((p >> 1) ? 8 : 0);
            float vx = As[row * PADA + cc], vy = As[row * PADA + cc + 1];
            __half hx = __float2half_rn(vx), hy = __float2half_rn(vy);
            __half2 h2 = __halves2half2(hx, hy);
            __half2 l2 = __halves2half2(__float2half_rn(vx - __half2float(hx)),
                                        __float2half_rn(vy - __half2float(hy)));
            ah[ks][p] = *(uint32_t*)&h2;
            al[ks][p] = *(uint32_t*)&l2;
        }
    }

    float m0 = __int_as_float(0x7f800000), z0 = 0.f;
    float m1 = m0, z1 = 0.f;
    int i0 = 0, i1 = 0;

    for (int ct = 0; ct < 16; ct++) {
        __syncthreads();   // protect B reuse
        // stage B tile (128 codes x 64 ch, hi+lo), rows padded to 72 halfs (144B)
#pragma unroll
        for (int i = 0; i < 4; i++) {
            int idx = t + i * 256;             // 0..1023
            int code = idx >> 3, c8 = idx & 7;
            const uint4* srcH = (const uint4*)g_cbH16 + (size_t)(ct * 128 + code) * 8 + c8;
            const uint4* srcL = (const uint4*)g_cbL16 + (size_t)(ct * 128 + code) * 8 + c8;
            *(uint4*)((char*)Bh + code * 144 + c8 * 16) = *srcH;
            *(uint4*)((char*)Bl + code * 144 + c8 * 16) = *srcL;
        }
        __syncthreads();

        float acc[16][4];
#pragma unroll
        for (int n8 = 0; n8 < 16; n8++)
#pragma unroll
            for (int p = 0; p < 4; p++) acc[n8][p] = 0.f;

#pragma unroll
        for (int ks = 0; ks < 4; ks++) {
#pragma unroll
            for (int n8 = 0; n8 < 16; n8++) {
                int base = (n8 * 8 + g) * 36 + ks * 8 + t4;
                uint32_t bh0 = Bh[base], bh1 = Bh[base + 4];
                uint32_t bl0 = Bl[base], bl1 = Bl[base + 4];
                mma16816(acc[n8], ah[ks][0], ah[ks][1], ah[ks][2], ah[ks][3], bh0, bh1);
                mma16816(acc[n8], ah[ks][0], ah[ks][1], ah[ks][2], ah[ks][3], bl0, bl1);
                mma16816(acc[n8], al[ks][0], al[ks][1], al[ks][2], al[ks][3], bh0, bh1);
            }
        }

        // epilogue: distance + stats + STG.64
#pragma unroll
        for (int n8 = 0; n8 < 16; n8++) {
            int col = ct * 128 + n8 * 8 + 2 * t4;
            float2 cs = *(float2*)&csqs[col];
            float d00 = fmaf(-2.f, acc[n8][0], xs0 + cs.x);
            float d01 = fmaf(-2.f, acc[n8][1], xs0 + cs.y);
            float d10 = fmaf(-2.f, acc[n8][2], xs1 + cs.x);
            float d11 = fmaf(-2.f, acc[n8][3], xs1 + cs.y);
            *(float2*)(out + DIST_OFF + (size_t)(n0 + r0) * KCB + col)     = make_float2(d00, d01);
            *(float2*)(out + DIST_OFF + (size_t)(n0 + r0 + 8) * KCB + col) = make_float2(d10, d11);
            if (fminf(d00, d01) < m0 + 4.0f) {
                bool lt = d00 < m0;
                float e = __expf((fminf(d00, m0) - fmaxf(d00, m0)) * INVT);
                z0 = lt ? fmaf(z0, e, 1.0f) : (z0 + e);
                i0 = lt ? col : i0;
                m0 = fminf(m0, d00);
                lt = d01 < m0;
                e = __expf((fminf(d01, m0) - fmaxf(d01, m0)) * INVT);
                z0 = lt ? fmaf(z0, e, 1.0f) : (z0 + e);
                i0 = lt ? (col + 1) : i0;
                m0 = fminf(m0, d01);
            }
            if (fminf(d10, d11) < m1 + 4.0f) {
                bool lt = d10 < m1;
                float e = __expf((fminf(d10, m1) - fmaxf(d10, m1)) * INVT);
                z1 = lt ? fmaf(z1, e, 1.0f) : (z1 + e);
                i1 = lt ? col : i1;
                m1 = fminf(m1, d10);
                lt = d11 < m1;
                e = __expf((fminf(d11, m1) - fmaxf(d11, m1)) * INVT);
                z1 = lt ? fmaf(z1, e, 1.0f) : (z1 + e);
                i1 = lt ? (col + 1) : i1;
                m1 = fminf(m1, d11);
            }
        }
    }

    // reduce (m,z,argmin) over the 4-lane quad (same rows)
#pragma unroll
    for (int o = 1; o <= 2; o <<= 1) {
        float m2 = __shfl_xor_sync(0xffffffffu, m0, o);
        float z2 = __shfl_xor_sync(0xffffffffu, z0, o);
        int   j2 = __shfl_xor_sync(0xffffffffu, i0, o);
        float mn = fminf(m0, m2);
        z0 = z0 * __expf((mn - m0) * INVT) + z2 * __expf((mn - m2) * INVT);
        i0 = (m2 < m0) ? j2 : i0;
        m0 = mn;
        m2 = __shfl_xor_sync(0xffffffffu, m1, o);
        z2 = __shfl_xor_sync(0xffffffffu, z1, o);
        j2 = __shfl_xor_sync(0xffffffffu, i1, o);
        mn = fminf(m1, m2);
        z1 = z1 * __expf((mn - m1) * INVT) + z2 * __expf((mn - m2) * INVT);
        i1 = (m2 < m1) ? j2 : i1;
        m1 = mn;
    }
    if (t4 == 0) {
        g_rowmin[n0 + r0] = m0;  g_z[n0 + r0] = z0;
        atomicAdd(out + VQ_OFF + i0, 1.0f);
        g_rowmin[n0 + r0 + 8] = m1;  g_z[n0 + r0 + 8] = z1;
        atomicAdd(out + VQ_OFF + i1, 1.0f);
    }
}

// ---------------- K2: probs -> transposed assignment + q_feat (single pass) ----------------
// 784 CTAs x 32 rows, 256 threads, k-tile 128.  (unchanged — validated R3/R4)
__global__ __launch_bounds__(256) void k2_softmax(const float* __restrict__ cbk,
                                                  float* __restrict__ out) {
    __shared__ float sT[128 * 32];
    __shared__ float qacc[32 * 65];
    __shared__ float listP[32 * 64];
    __shared__ int   listK[32 * 64];
    __shared__ int   cnt[32];
    __shared__ float minv[32], zinv[32];

    const int t = threadIdx.x;
    const int row = t >> 3, sub = t & 7;
    const int n0 = blockIdx.x * 32;
    const int b = n0 / HW, hw0 = n0 % HW;
    const float* dist = out + DIST_OFF + (size_t)n0 * KCB;

    if (t < 32) {
        minv[t] = g_rowmin[n0 + t];
        zinv[t] = __frcp_rn(g_z[n0 + t]);
        cnt[t] = 0;
    }
#pragma unroll
    for (int i = 0; i < 9; i++) {
        int idx = t + i * 256;
        if (idx < 32 * 65) qacc[idx] = 0.f;
    }
    __syncthreads();
    const float m = minv[row];
    const float zi = zinv[row];

    float* assign = out + ASSIGN_OFF + (size_t)b * KCB * HW + hw0;
    for (int kt = 0; kt < KCB; kt += 128) {
        const float4* p4 = (const float4*)(dist + (size_t)row * KCB + kt + sub * 16);
        float4 v4[4];
#pragma unroll
        for (int i = 0; i < 4; i++) v4[i] = p4[i];
        const float* v = (const float*)v4;
#pragma unroll
        for (int q = 0; q < 16; q++) {
            float p = __expf((m - v[q]) * INVT) * zi;
            int kl = sub * 16 + q;
            sT[kl * 32 + ((sub * 4 + row) & 31)] = p;
            if (p > 1e-10f) {
                int pos = atomicAdd(&cnt[row], 1);
                if (pos < 64) {
                    listK[row * 64 + pos] = kt + kl;
                    listP[row * 64 + pos] = p;
                } else {
                    const float* cr = cbk + (size_t)(kt + kl) * 64;
#pragma unroll 8
                    for (int c2 = 0; c2 < 64; c2++)
                        atomicAdd(&qacc[row * 65 + c2], p * cr[c2]);
                }
            }
        }
        __syncthreads();
#pragma unroll
        for (int s = 0; s < 16; s++) {
            int kl = s * 8 + (t >> 5);
            int r2 = t & 31;
            assign[(size_t)(kt + kl) * HW + r2] = sT[kl * 32 + (((kl >> 4) * 4 + r2) & 31)];
        }
        __syncthreads();
    }

    const int wid = t >> 5, lane2 = t & 31;
#pragma unroll
    for (int rr = wid; rr < 32; rr += 8) {
        int n = min(cnt[rr], 64);
        float a0 = 0.f, a1 = 0.f;
        for (int e = 0; e < n; e++) {
            int k = listK[rr * 64 + e];
            float p = listP[rr * 64 + e];
            a0 = fmaf(p, cbk[(size_t)k * 64 + lane2], a0);
            a1 = fmaf(p, cbk[(size_t)k * 64 + 32 + lane2], a1);
        }
        qacc[rr * 65 + lane2] += a0;
        qacc[rr * 65 + 32 + lane2] += a1;
    }
    __syncthreads();

    float* of = out + OUTF_OFF + (size_t)b * BSTRIDE + hw0;
#pragma unroll
    for (int i = 0; i < 8; i++) {
        int idx = t + i * 256;
        int c2 = idx >> 5, r2 = idx & 31;
        of[(size_t)c2 * HW + r2] = qacc[r2 * 65 + c2];
    }
}

extern "C" void kernel_launch(void* const* d_in, const int* in_sizes, int n_in,
                              void* d_out, int out_size) {
    const float* feat = (const float*)d_in[0];
    const float* cbk  = (const float*)d_in[1];
    float* out = (float*)d_out;

    cudaFuncSetAttribute(k1_mma, cudaFuncAttributeMaxDynamicSharedMemorySize, K1_SMEM);

    k0_prep<<<128, 256>>>(cbk, out);
    k1_mma<<<NPTS / 128, 256, K1_SMEM>>>(feat, out);
    k2_softmax<<<NPTS / 32, 256>>>(cbk, out);
}

// round 7
// speedup vs baseline: 2.2272x; 1.0153x over previous
#include <cuda_runtime.h>
#include <cuda_fp16.h>
#include <cstdint>

// ---- problem constants ----
#define NPTS   25088          // 8*56*56
#define KCB    2048
#define CDIM   64
#define HW     3136           // 56*56
#define BSTRIDE 200704        // 64*3136

// output offsets (floats), tuple order: out_feat, assignment, distance, vq0_update
#define OUTF_OFF   0
#define ASSIGN_OFF 1605632
#define DIST_OFF   52985856
#define VQ_OFF     104366080

#define INVT 10.0f

__device__ float  g_rowmin[NPTS];
__device__ float  g_z[NPTS];
__device__ float  g_csq[KCB];
__device__ __half g_cbH16[KCB * CDIM];   // fp16 hi part of codebook
__device__ __half g_cbL16[KCB * CDIM];   // fp16 residual lo part

// ---------------- K0: fp16 hi/lo codebook split + csq + zero vq ----------------
__global__ void k0_prep(const float* __restrict__ cbk, float* __restrict__ out) {
    int gid = blockIdx.x * 256 + threadIdx.x;    // 0..32767
    int code = gid >> 4, f4 = gid & 15;
    float4 v = ((const float4*)cbk)[code * 16 + f4];
    __half hx = __float2half_rn(v.x), hy = __float2half_rn(v.y);
    __half hz = __float2half_rn(v.z), hw = __float2half_rn(v.w);
    __half lx = __float2half_rn(v.x - __half2float(hx));
    __half ly = __float2half_rn(v.y - __half2float(hy));
    __half lz = __float2half_rn(v.z - __half2float(hz));
    __half lw = __float2half_rn(v.w - __half2float(hw));
    ((__half2*)g_cbH16)[code * 32 + f4 * 2]     = __halves2half2(hx, hy);
    ((__half2*)g_cbH16)[code * 32 + f4 * 2 + 1] = __halves2half2(hz, hw);
    ((__half2*)g_cbL16)[code * 32 + f4 * 2]     = __halves2half2(lx, ly);
    ((__half2*)g_cbL16)[code * 32 + f4 * 2 + 1] = __halves2half2(lz, lw);
    float p = v.x * v.x + v.y * v.y + v.z * v.z + v.w * v.w;
#pragma unroll
    for (int o = 8; o >= 1; o >>= 1) p += __shfl_xor_sync(0xffffffffu, p, o);
    if (f4 == 0) {
        g_csq[code] = p;
        out[VQ_OFF + code] = 0.0f;
    }
}

// ---------------- K1: mma.sync fp16 3-term distance GEMM + fused stats ----------------
// 196 CTAs x 128 rows, 256 threads (8 warps x 16 rows), 16 col-tiles of 128 codes.
// Epilogue split into two 64-col halves -> acc regs halved -> occupancy 2.
__device__ __forceinline__ void mma16816(float* c, uint32_t a0, uint32_t a1, uint32_t a2,
                                         uint32_t a3, uint32_t b0, uint32_t b1) {
    asm volatile(
        "mma.sync.aligned.m16n8k16.row.col.f32.f16.f16.f32 "
        "{%0,%1,%2,%3}, {%4,%5,%6,%7}, {%8,%9}, {%0,%1,%2,%3};"
        : "+f"(c[0]), "+f"(c[1]), "+f"(c[2]), "+f"(c[3])
        : "r"(a0), "r"(a1), "r"(a2), "r"(a3), "r"(b0), "r"(b1));
}

// smem layout (bytes)
#define PADA 68                          // floats per A row
#define SM_A    0                        // 128*68*4   = 34816
#define SM_CSQ  34816                    // 8192
#define SM_BH   43008                    // 128*36*4   = 18432
#define SM_BL   61440                    // 18432
#define K1_SMEM 79872

__global__ __launch_bounds__(256, 2) void k1_mma(const float* __restrict__ feat,
                                                 float* __restrict__ out) {
    extern __shared__ char sm[];
    float*    As   = (float*)(sm + SM_A);
    float*    csqs = (float*)(sm + SM_CSQ);
    uint32_t* Bh   = (uint32_t*)(sm + SM_BH);
    uint32_t* Bl   = (uint32_t*)(sm + SM_BL);

    const int t = threadIdx.x;
    const int wid = t >> 5, lane = t & 31;
    const int g = lane >> 2, t4 = lane & 3;
    const int n0 = blockIdx.x * 128;

    // stage A fp32 [row][ch] padded
#pragma unroll
    for (int i = 0; i < 32; i++) {
        int idx = t + i * 256;
        int ch = idx >> 7, row = idx & 127;
        int n = n0 + row, b = n / HW, hw = n - b * HW;
        As[row * PADA + ch] = feat[(size_t)b * BSTRIDE + (size_t)ch * HW + hw];
    }
#pragma unroll
    for (int i = 0; i < 2; i++) {
        int idx = t + i * 256;
        ((float4*)csqs)[idx] = ((const float4*)g_csq)[idx];
    }
    __syncthreads();

    const int r0 = wid * 16 + g;      // rows r0 and r0+8
    float xs0 = 0.f, xs1 = 0.f;
#pragma unroll 16
    for (int c = 0; c < 64; c++) {
        float v0 = As[r0 * PADA + c], v1 = As[(r0 + 8) * PADA + c];
        xs0 = fmaf(v0, v0, xs0);
        xs1 = fmaf(v1, v1, xs1);
    }

    // resident A fragments (hi/lo), 4 k-steps
    uint32_t ah[4][4], al[4][4];
#pragma unroll
    for (int ks = 0; ks < 4; ks++) {
        int c0 = ks * 16 + 2 * t4;
#pragma unroll
        for (int p = 0; p < 4; p++) {
            int row = (p & 1) ? (r0 + 8) : r0;
            int cc = c0 + ((p >> 1) ? 8 : 0);
            float vx = As[row * PADA + cc], vy = As[row * PADA + cc + 1];
            __half hx = __float2half_rn(vx), hy = __float2half_rn(vy);
            __half2 h2 = __halves2half2(hx, hy);
            __half2 l2 = __halves2half2(__float2half_rn(vx - __half2float(hx)),
                                        __float2half_rn(vy - __half2float(hy)));
            ah[ks][p] = *(uint32_t*)&h2;
            al[ks][p] = *(uint32_t*)&l2;
        }
    }

    float m0 = __int_as_float(0x7f800000), z0 = 0.f;
    float m1 = m0, z1 = 0.f;
    int i0 = 0, i1 = 0;

    for (int ct = 0; ct < 16; ct++) {
        __syncthreads();   // protect B reuse
        // stage B tile (128 codes x 64 ch, hi+lo), rows padded to 72 halfs (144B)
#pragma unroll
        for (int i = 0; i < 4; i++) {
            int idx = t + i * 256;             // 0..1023
            int code = idx >> 3, c8 = idx & 7;
            const uint4* srcH = (const uint4*)g_cbH16 + (size_t)(ct * 128 + code) * 8 + c8;
            const uint4* srcL = (const uint4*)g_cbL16 + (size_t)(ct * 128 + code) * 8 + c8;
            *(uint4*)((char*)Bh + code * 144 + c8 * 16) = *srcH;
            *(uint4*)((char*)Bl + code * 144 + c8 * 16) = *srcL;
        }
        __syncthreads();

#pragma unroll
        for (int half = 0; half < 2; half++) {
            float acc[8][4];
#pragma unroll
            for (int j = 0; j < 8; j++)
#pragma unroll
                for (int p = 0; p < 4; p++) acc[j][p] = 0.f;

#pragma unroll
            for (int ks = 0; ks < 4; ks++) {
#pragma unroll
                for (int j = 0; j < 8; j++) {
                    int n8 = half * 8 + j;
                    int base = (n8 * 8 + g) * 36 + ks * 8 + t4;
                    uint32_t bh0 = Bh[base], bh1 = Bh[base + 4];
                    uint32_t bl0 = Bl[base], bl1 = Bl[base + 4];
                    mma16816(acc[j], ah[ks][0], ah[ks][1], ah[ks][2], ah[ks][3], bh0, bh1);
                    mma16816(acc[j], ah[ks][0], ah[ks][1], ah[ks][2], ah[ks][3], bl0, bl1);
                    mma16816(acc[j], al[ks][0], al[ks][1], al[ks][2], al[ks][3], bh0, bh1);
                }
            }

            // epilogue: distance + stats + STG.64
#pragma unroll
            for (int j = 0; j < 8; j++) {
                int col = ct * 128 + (half * 8 + j) * 8 + 2 * t4;
                float2 cs = *(float2*)&csqs[col];
                float d00 = fmaf(-2.f, acc[j][0], xs0 + cs.x);
                float d01 = fmaf(-2.f, acc[j][1], xs0 + cs.y);
                float d10 = fmaf(-2.f, acc[j][2], xs1 + cs.x);
                float d11 = fmaf(-2.f, acc[j][3], xs1 + cs.y);
                *(float2*)(out + DIST_OFF + (size_t)(n0 + r0) * KCB + col)     = make_float2(d00, d01);
                *(float2*)(out + DIST_OFF + (size_t)(n0 + r0 + 8) * KCB + col) = make_float2(d10, d11);
                if (fminf(d00, d01) < m0 + 4.0f) {
                    bool lt = d00 < m0;
                    float e = __expf((fminf(d00, m0) - fmaxf(d00, m0)) * INVT);
                    z0 = lt ? fmaf(z0, e, 1.0f) : (z0 + e);
                    i0 = lt ? col : i0;
                    m0 = fminf(m0, d00);
                    lt = d01 < m0;
                    e = __expf((fminf(d01, m0) - fmaxf(d01, m0)) * INVT);
                    z0 = lt ? fmaf(z0, e, 1.0f) : (z0 + e);
                    i0 = lt ? (col + 1) : i0;
                    m0 = fminf(m0, d01);
                }
                if (fminf(d10, d11) < m1 + 4.0f) {
                    bool lt = d10 < m1;
                    float e = __expf((fminf(d10, m1) - fmaxf(d10, m1)) * INVT);
                    z1 = lt ? fmaf(z1, e, 1.0f) : (z1 + e);
                    i1 = lt ? col : i1;
                    m1 = fminf(m1, d10);
                    lt = d11 < m1;
                    e = __expf((fminf(d11, m1) - fmaxf(d11, m1)) * INVT);
                    z1 = lt ? fmaf(z1, e, 1.0f) : (z1 + e);
                    i1 = lt ? (col + 1) : i1;
                    m1 = fminf(m1, d11);
                }
            }
        }
    }

    // reduce (m,z,argmin) over the 4-lane quad (same rows)
#pragma unroll
    for (int o = 1; o <= 2; o <<= 1) {
        float m2 = __shfl_xor_sync(0xffffffffu, m0, o);
        float z2 = __shfl_xor_sync(0xffffffffu, z0, o);
        int   j2 = __shfl_xor_sync(0xffffffffu, i0, o);
        float mn = fminf(m0, m2);
        z0 = z0 * __expf((mn - m0) * INVT) + z2 * __expf((mn - m2) * INVT);
        i0 = (m2 < m0) ? j2 : i0;
        m0 = mn;
        m2 = __shfl_xor_sync(0xffffffffu, m1, o);
        z2 = __shfl_xor_sync(0xffffffffu, z1, o);
        j2 = __shfl_xor_sync(0xffffffffu, i1, o);
        mn = fminf(m1, m2);
        z1 = z1 * __expf((mn - m1) * INVT) + z2 * __expf((mn - m2) * INVT);
        i1 = (m2 < m1) ? j2 : i1;
        m1 = mn;
    }
    if (t4 == 0) {
        g_rowmin[n0 + r0] = m0;  g_z[n0 + r0] = z0;
        atomicAdd(out + VQ_OFF + i0, 1.0f);
        g_rowmin[n0 + r0 + 8] = m1;  g_z[n0 + r0 + 8] = z1;
        atomicAdd(out + VQ_OFF + i1, 1.0f);
    }
}

// ---------------- K2: probs -> transposed assignment + q_feat (single pass) ----------------
// 784 CTAs x 32 rows, 256 threads, k-tile 128. Group-skip exp for all-negligible groups.
__global__ __launch_bounds__(256) void k2_softmax(const float* __restrict__ cbk,
                                                  float* __restrict__ out) {
    __shared__ float sT[128 * 32];
    __shared__ float qacc[32 * 65];
    __shared__ float listP[32 * 64];
    __shared__ int   listK[32 * 64];
    __shared__ int   cnt[32];
    __shared__ float minv[32], zinv[32];

    const int t = threadIdx.x;
    const int row = t >> 3, sub = t & 7;
    const int n0 = blockIdx.x * 32;
    const int b = n0 / HW, hw0 = n0 % HW;
    const float* dist = out + DIST_OFF + (size_t)n0 * KCB;

    if (t < 32) {
        minv[t] = g_rowmin[n0 + t];
        zinv[t] = __frcp_rn(g_z[n0 + t]);
        cnt[t] = 0;
    }
#pragma unroll
    for (int i = 0; i < 9; i++) {
        int idx = t + i * 256;
        if (idx < 32 * 65) qacc[idx] = 0.f;
    }
    __syncthreads();
    const float m = minv[row];
    const float zi = zinv[row];

    float* assign = out + ASSIGN_OFF + (size_t)b * KCB * HW + hw0;
    for (int kt = 0; kt < KCB; kt += 128) {
        const float4* p4 = (const float4*)(dist + (size_t)row * KCB + kt + sub * 16);
        float4 v4[4];
#pragma unroll
        for (int i = 0; i < 4; i++) v4[i] = p4[i];
        const float* v = (const float*)v4;
        float vmin = v[0];
#pragma unroll
        for (int q = 1; q < 16; q++) vmin = fminf(vmin, v[q]);
        if (vmin < m + 3.2f) {   // some prob >= e^-32 in this group
#pragma unroll
            for (int q = 0; q < 16; q++) {
                float arg = (m - v[q]) * INVT;
                float p = (arg > -32.f) ? __expf(arg) * zi : 0.f;
                int kl = sub * 16 + q;
                sT[kl * 32 + ((sub * 4 + row) & 31)] = p;
                if (p > 1e-10f) {
                    int pos = atomicAdd(&cnt[row], 1);
                    if (pos < 64) {
                        listK[row * 64 + pos] = kt + kl;
                        listP[row * 64 + pos] = p;
                    } else {
                        const float* cr = cbk + (size_t)(kt + kl) * 64;
#pragma unroll 8
                        for (int c2 = 0; c2 < 64; c2++)
                            atomicAdd(&qacc[row * 65 + c2], p * cr[c2]);
                    }
                }
            }
        } else {                 // entire group negligible -> exact zeros
#pragma unroll
            for (int q = 0; q < 16; q++) {
                int kl = sub * 16 + q;
                sT[kl * 32 + ((sub * 4 + row) & 31)] = 0.f;
            }
        }
        __syncthreads();
#pragma unroll
        for (int s = 0; s < 16; s++) {
            int kl = s * 8 + (t >> 5);
            int r2 = t & 31;
            assign[(size_t)(kt + kl) * HW + r2] = sT[kl * 32 + (((kl >> 4) * 4 + r2) & 31)];
        }
        __syncthreads();
    }

    const int wid = t >> 5, lane2 = t & 31;
#pragma unroll
    for (int rr = wid; rr < 32; rr += 8) {
        int n = min(cnt[rr], 64);
        float a0 = 0.f, a1 = 0.f;
        for (int e = 0; e < n; e++) {
            int k = listK[rr * 64 + e];
            float p = listP[rr * 64 + e];
            a0 = fmaf(p, cbk[(size_t)k * 64 + lane2], a0);
            a1 = fmaf(p, cbk[(size_t)k * 64 + 32 + lane2], a1);
        }
        qacc[rr * 65 + lane2] += a0;
        qacc[rr * 65 + 32 + lane2] += a1;
    }
    __syncthreads();

    float* of = out + OUTF_OFF + (size_t)b * BSTRIDE + hw0;
#pragma unroll
    for (int i = 0; i < 8; i++) {
        int idx = t + i * 256;
        int c2 = idx >> 5, r2 = idx & 31;
        of[(size_t)c2 * HW + r2] = qacc[r2 * 65 + c2];
    }
}

extern "C" void kernel_launch(void* const* d_in, const int* in_sizes, int n_in,
                              void* d_out, int out_size) {
    const float* feat = (const float*)d_in[0];
    const float* cbk  = (const float*)d_in[1];
    float* out = (float*)d_out;

    cudaFuncSetAttribute(k1_mma, cudaFuncAttributeMaxDynamicSharedMemorySize, K1_SMEM);

    k0_prep<<<128, 256>>>(cbk, out);
    k1_mma<<<NPTS / 128, 256, K1_SMEM>>>(feat, out);
    k2_softmax<<<NPTS / 32, 256>>>(cbk, out);
}